// round 1
// baseline (speedup 1.0000x reference)
#include <cuda_runtime.h>
#include <cstdint>

// CARAFE: N=4, C=256, H=W=64, K=5, G=1, S=2  ->  out [4,256,128,128] f32
#define KK   5
#define PADW 2
#define TILE 8            // input cells per tile dim
#define PH   12           // TILE + KK - 1
#define PSTR 24           // padded patch row stride: 24*r mod 32 = {0,24,16,8} -> conflict-free
#define CHPATCH (PH * PSTR)   // 288 floats per channel patch
#define NCH_STAGE 8
#define NSTAGE 32         // 256 channels / 8
#define NTHREADS 256
#define NLOAD (NCH_STAGE * PH * PH)   // 1152 elements cooperatively loaded per stage

#define N_ 4
#define C_ 256
#define H_ 64
#define W_ 64
#define HO 128
#define WO 128

__device__ __forceinline__ unsigned long long pack2(float lo, float hi) {
    unsigned long long r;
    asm("mov.b64 %0, {%1, %2};" : "=l"(r) : "f"(lo), "f"(hi));
    return r;
}
__device__ __forceinline__ void ffma2(unsigned long long& d, unsigned long long a,
                                      unsigned long long b) {
    // packed 2xfp32 FMA (Blackwell f32x2 pipe, 2x scalar FFMA throughput)
    asm("fma.rn.f32x2 %0, %1, %2, %0;" : "+l"(d) : "l"(a), "l"(b));
}

__global__ void __launch_bounds__(NTHREADS, 1)
carafe_kernel(const float* __restrict__ feat, const float* __restrict__ masks,
              float* __restrict__ out)
{
    __shared__ float sbuf[2][NCH_STAGE * CHPATCH];   // 2 * 8 * 288 * 4B = 18432 B

    const int t      = threadIdx.x;
    const int lane_c = t >> 6;        // 0..3  (constant within a warp)
    const int cid    = t & 63;        // cell id in 8x8 tile
    const int ww     = cid & 7;
    const int hh     = cid >> 3;

    const int blk  = blockIdx.x;      // 0..255
    const int tile = blk & 63;
    const int n    = blk >> 6;
    const int th   = tile >> 3, tw = tile & 7;
    const int h0   = th * TILE, w0 = tw * TILE;
    const int oh   = (h0 + hh) * 2, ow = (w0 + ww) * 2;

    // ---- per-thread masks: 25 taps x 2 output rows, packed over q (adjacent cols) ----
    unsigned long long m0[25], m1[25];
    {
        const float* mb = masks + (size_t)n * 25 * (HO * WO) + (size_t)oh * WO + ow;
        #pragma unroll
        for (int k = 0; k < 25; ++k) {
            float2 a = __ldg((const float2*)(mb + (size_t)k * (HO * WO)));
            float2 b = __ldg((const float2*)(mb + (size_t)k * (HO * WO) + WO));
            m0[k] = pack2(a.x, a.y);
            m1[k] = pack2(b.x, b.y);
        }
    }

    // ---- precompute cooperative-load slots (5 per thread max) ----
    const float* fbase = feat + (size_t)n * (C_ * H_ * W_);
    int  sofs[5];
    int  gofs[5];
    #pragma unroll
    for (int i = 0; i < 5; ++i) {
        const int e = t + i * NTHREADS;
        if (e < NLOAD) {
            const int ch  = e / (PH * PH);
            const int rem = e - ch * (PH * PH);
            const int r   = rem / PH;
            const int col = rem - r * PH;
            const int gr  = h0 - PADW + r;
            const int gc  = w0 - PADW + col;
            sofs[i] = ch * CHPATCH + r * PSTR + col;
            gofs[i] = ((unsigned)gr < (unsigned)H_ && (unsigned)gc < (unsigned)W_)
                          ? (ch * (H_ * W_) + gr * W_ + gc)
                          : -1;
        } else {
            sofs[i] = -1;
            gofs[i] = -1;
        }
    }

    float v[5];

    // prologue: stage 0 into buffer 0
    #pragma unroll
    for (int i = 0; i < 5; ++i)
        v[i] = (gofs[i] >= 0) ? __ldg(fbase + gofs[i]) : 0.f;
    #pragma unroll
    for (int i = 0; i < 5; ++i)
        if (sofs[i] >= 0) sbuf[0][sofs[i]] = v[i];
    __syncthreads();

    float* obase = out + (size_t)n * (C_ * HO * WO);

    for (int s = 0; s < NSTAGE; ++s) {
        const int c0 = s * NCH_STAGE;

        // issue next stage's global loads early (latency hidden under compute)
        if (s + 1 < NSTAGE) {
            const float* fb = fbase + (size_t)(c0 + NCH_STAGE) * (H_ * W_);
            #pragma unroll
            for (int i = 0; i < 5; ++i)
                v[i] = (gofs[i] >= 0) ? __ldg(fb + gofs[i]) : 0.f;
        }

        // compute 2 channels x 2x2 output pixels, f32x2-packed over q
        const float* fA = &sbuf[s & 1][0] + lane_c * CHPATCH + hh * PSTR + ww;
        const float* fB = fA + 4 * CHPATCH;
        unsigned long long aA0 = 0, aA1 = 0, aB0 = 0, aB1 = 0;
        #pragma unroll
        for (int ki = 0; ki < KK; ++ki) {
            #pragma unroll
            for (int kj = 0; kj < KK; ++kj) {
                const int k = ki * KK + kj;
                const float a = fA[ki * PSTR + kj];
                const float b = fB[ki * PSTR + kj];
                const unsigned long long pa = pack2(a, a);
                const unsigned long long pb = pack2(b, b);
                ffma2(aA0, pa, m0[k]);
                ffma2(aA1, pa, m1[k]);
                ffma2(aB0, pb, m0[k]);
                ffma2(aB1, pb, m1[k]);
            }
        }

        const int cA = c0 + lane_c;
        const int cB = cA + 4;
        unsigned long long* oA =
            (unsigned long long*)(obase + ((size_t)cA * HO + oh) * WO + ow);
        unsigned long long* oB =
            (unsigned long long*)(obase + ((size_t)cB * HO + oh) * WO + ow);
        oA[0]      = aA0;
        oA[WO / 2] = aA1;   // next output row
        oB[0]      = aB0;
        oB[WO / 2] = aB1;

        // commit prefetched data into the other buffer
        if (s + 1 < NSTAGE) {
            float* dst = &sbuf[(s + 1) & 1][0];
            #pragma unroll
            for (int i = 0; i < 5; ++i)
                if (sofs[i] >= 0) dst[sofs[i]] = v[i];
        }
        __syncthreads();
    }
}

extern "C" void kernel_launch(void* const* d_in, const int* in_sizes, int n_in,
                              void* d_out, int out_size) {
    const float* feat  = (const float*)d_in[0];
    const float* masks = (const float*)d_in[1];
    // defensive: identify tensors by element count (features 4*256*64*64, masks 4*25*128*128)
    if (n_in >= 2 && in_sizes[0] == N_ * KK * KK * HO * WO &&
        in_sizes[1] == N_ * C_ * H_ * W_) {
        const float* tmp = feat; feat = masks; masks = tmp;
    }
    carafe_kernel<<<N_ * 64, NTHREADS>>>(feat, masks, (float*)d_out);
}

// round 2
// speedup vs baseline: 1.4476x; 1.4476x over previous
#include <cuda_runtime.h>
#include <cstdint>

// CARAFE: N=4, C=256, H=W=64, K=5, G=1, S=2  ->  out [4,256,128,128] f32
#define KK   5
#define N_   4
#define C_   256
#define H_   64
#define W_   64
#define HO   128
#define WO   128

#define TH_CELLS 4         // input cells per block (rows)
#define TW_CELLS 8         // input cells per block (cols)
#define PR 8               // patch rows  = TH_CELLS + KK - 1
#define PC 12              // patch cols  = TW_CELLS + KK - 1
#define PS 13              // row stride in float2 units (odd; conflict stagger)
#define PAIR_F (PR * PS * 2)      // 208 floats per channel-pair patch
#define STAGE_F (4 * PAIR_F)      // 832 floats per stage buffer (8 channels)
#define NTHREADS 128
#define NSTAGE 32                 // 256 channels / 8 per stage
#define NLOAD (8 * PR * PC)       // 768 feature elements per stage
#define LPT (NLOAD / NTHREADS)    // 6 loads per thread

typedef unsigned long long ull;

__device__ __forceinline__ ull pack2(float lo, float hi) {
    ull r;
    asm("mov.b64 %0, {%1, %2};" : "=l"(r) : "f"(lo), "f"(hi));
    return r;
}
__device__ __forceinline__ void unpack2(float& lo, float& hi, ull v) {
    asm("mov.b64 {%0, %1}, %2;" : "=f"(lo), "=f"(hi) : "l"(v));
}
__device__ __forceinline__ void ffma2(ull& d, ull a, ull b) {
    // packed 2xfp32 FMA (Blackwell f32x2 pipe)
    asm("fma.rn.f32x2 %0, %1, %2, %0;" : "+l"(d) : "l"(a), "l"(b));
}

__global__ void __launch_bounds__(NTHREADS, 4)
carafe_kernel(const float* __restrict__ feat, const float* __restrict__ masks,
              float* __restrict__ out)
{
    __shared__ __align__(16) float sbuf[2][STAGE_F];   // 2*832*4 = 6656 B

    const int t    = threadIdx.x;
    const int oh_l = t >> 4;          // 0..7  local output row
    const int ow_l = t & 15;          // 0..15 local output col
    const int hh   = oh_l >> 1;       // input cell row 0..3
    const int wwq  = ow_l >> 1;       // input cell col 0..7

    const int b    = blockIdx.x;      // 0..511
    const int n    = b >> 7;
    const int tidx = b & 127;
    const int th   = tidx >> 3;       // 0..15
    const int tw   = tidx & 7;        // 0..7
    const int h0   = th * TH_CELLS;
    const int w0   = tw * TW_CELLS;
    const int oh   = th * (2 * TH_CELLS) + oh_l;
    const int ow   = tw * (2 * TW_CELLS) + ow_l;

    // ---- per-thread masks (one output pixel), pre-duplicated for channel-packed FFMA2 ----
    ull m[25];
    {
        const float* mb = masks + (size_t)n * 25 * (HO * WO) + (size_t)oh * WO + ow;
        #pragma unroll
        for (int k = 0; k < 25; ++k) {
            const float mv = __ldg(mb + (size_t)k * (HO * WO));
            m[k] = pack2(mv, mv);
        }
    }

    // ---- cooperative-load slots: interleaved (ch&1) channel-pair layout ----
    const float* fbase = feat + (size_t)n * (C_ * H_ * W_);
    int sofs[LPT], gofs[LPT];
    #pragma unroll
    for (int i = 0; i < LPT; ++i) {
        const int e   = t + i * NTHREADS;          // < 768
        const int ch  = e / (PR * PC);
        const int rem = e - ch * (PR * PC);
        const int r   = rem / PC;
        const int col = rem - r * PC;
        const int gr  = h0 - 2 + r;
        const int gc  = w0 - 2 + col;
        sofs[i] = (ch >> 1) * PAIR_F + r * (PS * 2) + col * 2 + (ch & 1);
        gofs[i] = ((unsigned)gr < (unsigned)H_ && (unsigned)gc < (unsigned)W_)
                      ? (ch * (H_ * W_) + gr * W_ + gc)
                      : -1;
    }

    float v[LPT];

    // prologue: stage 0 -> buffer 0
    #pragma unroll
    for (int i = 0; i < LPT; ++i)
        v[i] = (gofs[i] >= 0) ? __ldg(fbase + gofs[i]) : 0.f;
    #pragma unroll
    for (int i = 0; i < LPT; ++i)
        sbuf[0][sofs[i]] = v[i];
    __syncthreads();

    float* obase = out + (size_t)n * (C_ * HO * WO) + (size_t)oh * WO + ow;

    for (int s = 0; s < NSTAGE; ++s) {
        // prefetch next stage's features (latency hidden under compute)
        if (s + 1 < NSTAGE) {
            const float* fb = fbase + (size_t)(s + 1) * 8 * (H_ * W_);
            #pragma unroll
            for (int i = 0; i < LPT; ++i)
                v[i] = (gofs[i] >= 0) ? __ldg(fb + gofs[i]) : 0.f;
        }

        // compute: 4 channel pairs x 25 taps, LDS.64 + FFMA2 each
        const float* sb = &sbuf[s & 1][0] + hh * (PS * 2) + wwq * 2;
        ull a0 = 0, a1 = 0, a2 = 0, a3 = 0;
        #pragma unroll
        for (int ki = 0; ki < KK; ++ki) {
            #pragma unroll
            for (int kj = 0; kj < KK; ++kj) {
                const int k   = ki * KK + kj;
                const int off = ki * (PS * 2) + kj * 2;
                const ull f0 = *(const ull*)(sb + 0 * PAIR_F + off);
                const ull f1 = *(const ull*)(sb + 1 * PAIR_F + off);
                const ull f2 = *(const ull*)(sb + 2 * PAIR_F + off);
                const ull f3 = *(const ull*)(sb + 3 * PAIR_F + off);
                ffma2(a0, f0, m[k]);
                ffma2(a1, f1, m[k]);
                ffma2(a2, f2, m[k]);
                ffma2(a3, f3, m[k]);
            }
        }

        // stores: 8 channels, channel-strided (coalesced across the warp)
        {
            const int c0 = s * 8;
            float lo, hi;
            unpack2(lo, hi, a0);
            obase[(size_t)(c0 + 0) * (HO * WO)] = lo;
            obase[(size_t)(c0 + 1) * (HO * WO)] = hi;
            unpack2(lo, hi, a1);
            obase[(size_t)(c0 + 2) * (HO * WO)] = lo;
            obase[(size_t)(c0 + 3) * (HO * WO)] = hi;
            unpack2(lo, hi, a2);
            obase[(size_t)(c0 + 4) * (HO * WO)] = lo;
            obase[(size_t)(c0 + 5) * (HO * WO)] = hi;
            unpack2(lo, hi, a3);
            obase[(size_t)(c0 + 6) * (HO * WO)] = lo;
            obase[(size_t)(c0 + 7) * (HO * WO)] = hi;
        }

        // commit prefetched data to the other buffer
        if (s + 1 < NSTAGE) {
            float* dst = &sbuf[(s + 1) & 1][0];
            #pragma unroll
            for (int i = 0; i < LPT; ++i)
                dst[sofs[i]] = v[i];
        }
        __syncthreads();
    }
}

extern "C" void kernel_launch(void* const* d_in, const int* in_sizes, int n_in,
                              void* d_out, int out_size) {
    const float* feat  = (const float*)d_in[0];
    const float* masks = (const float*)d_in[1];
    // defensive: identify tensors by element count
    if (n_in >= 2 && in_sizes[0] == N_ * KK * KK * HO * WO &&
        in_sizes[1] == N_ * C_ * H_ * W_) {
        const float* tmp = feat; feat = masks; masks = tmp;
    }
    carafe_kernel<<<N_ * 128, NTHREADS>>>(feat, masks, (float*)d_out);
}